// round 1
// baseline (speedup 1.0000x reference)
#include <cuda_runtime.h>
#include <math.h>

#define SQ     2048
#define BATCH  2
#define HID    4096
#define QKV_O  6144
#define NHEADS 32
#define KVH    8
#define HD     128

// Scratch (allocation-free rule: __device__ globals)
__device__ float g_qkv[(size_t)BATCH * SQ * QKV_O];   // ~100 MB
__device__ float g_attn[(size_t)BATCH * SQ * HID];    // ~67 MB

// ---------------------------------------------------------------------------
// SGEMM: C[M,N] = A[M,K] * B[N,K]^T   (A, B both row-major, K contiguous)
// 128x128 block tile, BK=16, 256 threads, 8x8 per thread.
// ---------------------------------------------------------------------------
template<int BM, int BN, int BK, int TM, int TN>
__global__ void __launch_bounds__(256, 2) sgemm_nt(
    const float* __restrict__ A, const float* __restrict__ B,
    float* __restrict__ C, int M, int N, int K)
{
    __shared__ float As[BK][BM + 4];
    __shared__ float Bs[BK][BN + 4];

    const int tid = threadIdx.x;
    const int tx = tid & 15;
    const int ty = tid >> 4;
    const int rowBase = blockIdx.y * BM;
    const int colBase = blockIdx.x * BN;

    const float* Ab = A + (size_t)rowBase * K;
    const float* Bb = B + (size_t)colBase * K;

    float acc[TM][TN];
    #pragma unroll
    for (int i = 0; i < TM; ++i)
        #pragma unroll
        for (int j = 0; j < TN; ++j) acc[i][j] = 0.f;

    float ar[TM], br[TN];

    for (int k0 = 0; k0 < K; k0 += BK) {
        // Load A tile (BM x BK) -> As[k][m]  (transposed)
        #pragma unroll
        for (int it = 0; it < (BM * BK) / (256 * 4); ++it) {
            int idx = tid + it * 256;           // 0..511
            int r   = idx >> 2;                 // row 0..127
            int kq  = (idx & 3) * 4;            // k sub 0,4,8,12
            float4 v = *(const float4*)(Ab + (size_t)r * K + k0 + kq);
            As[kq + 0][r] = v.x;
            As[kq + 1][r] = v.y;
            As[kq + 2][r] = v.z;
            As[kq + 3][r] = v.w;
        }
        // Load B tile (BN x BK) -> Bs[k][n]
        #pragma unroll
        for (int it = 0; it < (BN * BK) / (256 * 4); ++it) {
            int idx = tid + it * 256;
            int r   = idx >> 2;
            int kq  = (idx & 3) * 4;
            float4 v = *(const float4*)(Bb + (size_t)r * K + k0 + kq);
            Bs[kq + 0][r] = v.x;
            Bs[kq + 1][r] = v.y;
            Bs[kq + 2][r] = v.z;
            Bs[kq + 3][r] = v.w;
        }
        __syncthreads();

        #pragma unroll
        for (int k = 0; k < BK; ++k) {
            #pragma unroll
            for (int i = 0; i < TM; ++i) ar[i] = As[k][ty * TM + i];
            #pragma unroll
            for (int j = 0; j < TN; ++j) br[j] = Bs[k][tx * TN + j];
            #pragma unroll
            for (int i = 0; i < TM; ++i)
                #pragma unroll
                for (int j = 0; j < TN; ++j)
                    acc[i][j] += ar[i] * br[j];
        }
        __syncthreads();
    }

    #pragma unroll
    for (int i = 0; i < TM; ++i) {
        size_t r = (size_t)(rowBase + ty * TM + i);
        #pragma unroll
        for (int j = 0; j < TN; j += 4) {
            float4 v = make_float4(acc[i][j], acc[i][j+1], acc[i][j+2], acc[i][j+3]);
            *(float4*)(C + r * N + colBase + tx * TN + j) = v;
        }
    }
}

// ---------------------------------------------------------------------------
// RoPE applied in-place to Q (heads 0..31) and K (heads 32..39) inside g_qkv.
// One thread per (row, head, pair).
// ---------------------------------------------------------------------------
__global__ void rope_kernel(float* __restrict__ qkv, const int* __restrict__ positions)
{
    int idx = blockIdx.x * blockDim.x + threadIdx.x;
    int p = idx & 63;
    int h = (idx >> 6) % 40;
    int r = idx / (64 * 40);
    if (r >= BATCH * SQ) return;

    int col = (h < NHEADS) ? h * HD : HID + (h - NHEADS) * HD;
    float* base = qkv + (size_t)r * QKV_O + col;

    float pos = (float)positions[r];
    // inv_freq = theta^(-p/64) = exp(-p * ln(1e6)/64)
    float inv = expf((float)p * (-13.815510557964274f / 64.f));
    float ang = pos * inv;
    float sn, cs;
    sincosf(ang, &sn, &cs);

    float x1 = base[p];
    float x2 = base[p + 64];
    base[p]      = x1 * cs - x2 * sn;
    base[p + 64] = x2 * cs + x1 * sn;
}

// ---------------------------------------------------------------------------
// Flash attention, fp32, causal, GQA (R=4). BM=BN=64, D=128, 256 threads.
// Thread grid 16x16: scores 4x4/thread, O 4 rows x 8 cols/thread.
// Row state (m, l) lives in registers, duplicated across the tx group.
// ---------------------------------------------------------------------------
#define BMA 64
#define BNA 64
#define QK_LD 65     // padded stride for Qs/Ks [d][m]
#define PS_LD 68     // padded stride for Ps [m][n]

__global__ void __launch_bounds__(256, 2) attn_kernel(
    const float* __restrict__ qkv, float* __restrict__ attn_out)
{
    extern __shared__ float sm[];
    float* Qs = sm;                       // [128][QK_LD]
    float* Ks = Qs + 128 * QK_LD;         // [128][QK_LD]; later aliased by Ps
    float* Vs = Ks + 128 * QK_LD;         // [64][128]
    float* Ps = Ks;                       // [64][PS_LD] (fits inside Ks region)

    const int tid = threadIdx.x;
    const int tx = tid & 15;
    const int ty = tid >> 4;
    const int qt = blockIdx.x;
    const int h  = blockIdx.y;
    const int b  = blockIdx.z;
    const int g  = h >> 2;   // KV head
    const float scale = 0.08838834764831845f;  // 1/sqrt(128)

    const float* qbase = qkv + ((size_t)(b * SQ + qt * BMA)) * QKV_O + h * HD;
    const float* kbase = qkv + ((size_t)(b * SQ)) * QKV_O + HID + g * HD;
    const float* vbase = qkv + ((size_t)(b * SQ)) * QKV_O + HID + KVH * HD + g * HD;

    // Load Q tile transposed & pre-scaled: Qs[d][m]
    for (int i = tid; i < BMA * 32; i += 256) {
        int n  = i >> 5;
        int d4 = (i & 31) * 4;
        float4 v = *(const float4*)(qbase + (size_t)n * QKV_O + d4);
        Qs[(d4 + 0) * QK_LD + n] = v.x * scale;
        Qs[(d4 + 1) * QK_LD + n] = v.y * scale;
        Qs[(d4 + 2) * QK_LD + n] = v.z * scale;
        Qs[(d4 + 3) * QK_LD + n] = v.w * scale;
    }

    float m_i[4], l_i[4], o[4][8];
    #pragma unroll
    for (int i = 0; i < 4; ++i) {
        m_i[i] = -1e30f; l_i[i] = 0.f;
        #pragma unroll
        for (int j = 0; j < 8; ++j) o[i][j] = 0.f;
    }

    const int nkt = qt + 1;   // causal: key tiles 0..qt
    for (int kt = 0; kt < nkt; ++kt) {
        __syncthreads();   // prior PV done with Ps/Vs; also orders Qs on first iter

        const float* kb = kbase + (size_t)(kt * BNA) * QKV_O;
        const float* vb = vbase + (size_t)(kt * BNA) * QKV_O;
        for (int i = tid; i < BNA * 32; i += 256) {
            int n  = i >> 5;
            int d4 = (i & 31) * 4;
            float4 v = *(const float4*)(kb + (size_t)n * QKV_O + d4);
            Ks[(d4 + 0) * QK_LD + n] = v.x;
            Ks[(d4 + 1) * QK_LD + n] = v.y;
            Ks[(d4 + 2) * QK_LD + n] = v.z;
            Ks[(d4 + 3) * QK_LD + n] = v.w;
            float4 w = *(const float4*)(vb + (size_t)n * QKV_O + d4);
            *(float4*)(Vs + n * 128 + d4) = w;
        }
        __syncthreads();

        // S = (Q*scale) K^T : 4x4 per thread
        float s[4][4];
        #pragma unroll
        for (int i = 0; i < 4; ++i)
            #pragma unroll
            for (int j = 0; j < 4; ++j) s[i][j] = 0.f;

        #pragma unroll 4
        for (int k = 0; k < 128; ++k) {
            float a[4], bb[4];
            #pragma unroll
            for (int i = 0; i < 4; ++i) a[i]  = Qs[k * QK_LD + ty * 4 + i];
            #pragma unroll
            for (int j = 0; j < 4; ++j) bb[j] = Ks[k * QK_LD + tx * 4 + j];
            #pragma unroll
            for (int i = 0; i < 4; ++i)
                #pragma unroll
                for (int j = 0; j < 4; ++j)
                    s[i][j] += a[i] * bb[j];
        }

        // Causal mask on diagonal tile (tile-local row/col indices match globals)
        if (kt == qt) {
            #pragma unroll
            for (int i = 0; i < 4; ++i) {
                int qrow = ty * 4 + i;
                #pragma unroll
                for (int j = 0; j < 4; ++j)
                    if (tx * 4 + j > qrow) s[i][j] = -1e30f;
            }
        }

        // Online softmax update (row group = 16 lanes with same ty, within warp)
        float alpha[4], pr[4][4];
        #pragma unroll
        for (int i = 0; i < 4; ++i) {
            float tm = fmaxf(fmaxf(s[i][0], s[i][1]), fmaxf(s[i][2], s[i][3]));
            tm = fmaxf(tm, __shfl_xor_sync(0xffffffffu, tm, 1));
            tm = fmaxf(tm, __shfl_xor_sync(0xffffffffu, tm, 2));
            tm = fmaxf(tm, __shfl_xor_sync(0xffffffffu, tm, 4));
            tm = fmaxf(tm, __shfl_xor_sync(0xffffffffu, tm, 8));
            float mn = fmaxf(m_i[i], tm);
            alpha[i] = __expf(m_i[i] - mn);
            float rs = 0.f;
            #pragma unroll
            for (int j = 0; j < 4; ++j) {
                pr[i][j] = __expf(s[i][j] - mn);
                rs += pr[i][j];
            }
            rs += __shfl_xor_sync(0xffffffffu, rs, 1);
            rs += __shfl_xor_sync(0xffffffffu, rs, 2);
            rs += __shfl_xor_sync(0xffffffffu, rs, 4);
            rs += __shfl_xor_sync(0xffffffffu, rs, 8);
            l_i[i] = l_i[i] * alpha[i] + rs;
            m_i[i] = mn;
        }

        __syncthreads();   // everyone done reading Ks before Ps overwrite

        #pragma unroll
        for (int i = 0; i < 4; ++i)
            *(float4*)(Ps + (ty * 4 + i) * PS_LD + tx * 4) =
                make_float4(pr[i][0], pr[i][1], pr[i][2], pr[i][3]);

        #pragma unroll
        for (int i = 0; i < 4; ++i)
            #pragma unroll
            for (int j = 0; j < 8; ++j) o[i][j] *= alpha[i];

        __syncthreads();

        // O += P @ V : rows ty*4+i, cols tx*8..tx*8+7
        #pragma unroll 2
        for (int kk = 0; kk < BNA; ++kk) {
            float p[4];
            #pragma unroll
            for (int i = 0; i < 4; ++i) p[i] = Ps[(ty * 4 + i) * PS_LD + kk];
            float4 va = *(const float4*)(Vs + kk * 128 + tx * 8);
            float4 vb4 = *(const float4*)(Vs + kk * 128 + tx * 8 + 4);
            #pragma unroll
            for (int i = 0; i < 4; ++i) {
                o[i][0] += p[i] * va.x;  o[i][1] += p[i] * va.y;
                o[i][2] += p[i] * va.z;  o[i][3] += p[i] * va.w;
                o[i][4] += p[i] * vb4.x; o[i][5] += p[i] * vb4.y;
                o[i][6] += p[i] * vb4.z; o[i][7] += p[i] * vb4.w;
            }
        }
    }

    // Epilogue: normalize and write [b, qrow, h*128 + col]
    float* ob = attn_out + ((size_t)(b * SQ + qt * BMA)) * HID + h * HD;
    #pragma unroll
    for (int i = 0; i < 4; ++i) {
        float inv = 1.f / l_i[i];
        float4 v0 = make_float4(o[i][0] * inv, o[i][1] * inv, o[i][2] * inv, o[i][3] * inv);
        float4 v1 = make_float4(o[i][4] * inv, o[i][5] * inv, o[i][6] * inv, o[i][7] * inv);
        *(float4*)(ob + (size_t)(ty * 4 + i) * HID + tx * 8)     = v0;
        *(float4*)(ob + (size_t)(ty * 4 + i) * HID + tx * 8 + 4) = v1;
    }
}

// ---------------------------------------------------------------------------
extern "C" void kernel_launch(void* const* d_in, const int* in_sizes, int n_in,
                              void* d_out, int out_size)
{
    const float* hs   = (const float*)d_in[0];   // [B,S,H]
    const int*   pos  = (const int*)  d_in[1];   // [B,S]
    const float* wqkv = (const float*)d_in[2];   // [6144,4096]
    const float* wo   = (const float*)d_in[3];   // [4096,4096]
    float* out = (float*)d_out;                  // [B,S,H]

    float *qkv, *attn;
    cudaGetSymbolAddress((void**)&qkv, g_qkv);
    cudaGetSymbolAddress((void**)&attn, g_attn);

    const int M = BATCH * SQ;   // 4096

    // 1) QKV projection: [4096,6144] = hs[4096,4096] @ wqkv^T
    sgemm_nt<128,128,16,8,8><<<dim3(QKV_O / 128, M / 128), 256>>>(
        hs, wqkv, qkv, M, QKV_O, HID);

    // 2) RoPE on Q + K heads
    {
        int total = M * 40 * 64;
        rope_kernel<<<(total + 255) / 256, 256>>>(qkv, pos);
    }

    // 3) Flash attention
    {
        size_t smem = (size_t)(128 * QK_LD * 2 + BNA * 128) * sizeof(float); // ~97 KB
        cudaFuncSetAttribute(attn_kernel,
                             cudaFuncAttributeMaxDynamicSharedMemorySize, (int)smem);
        attn_kernel<<<dim3(SQ / BMA, NHEADS, BATCH), 256, smem>>>(qkv, attn);
    }

    // 4) Output projection: out[4096,4096] = attn @ wo^T
    sgemm_nt<128,128,16,8,8><<<dim3(HID / 128, M / 128), 256>>>(
        attn, wo, out, M, HID, HID);
}

// round 4
// speedup vs baseline: 2.6617x; 2.6617x over previous
#include <cuda_runtime.h>
#include <cuda_fp16.h>
#include <math.h>
#include <stdint.h>

#define SQ     2048
#define BATCH  2
#define HID    4096
#define QKV_O  6144
#define NHEADS 32
#define KVH    8
#define HD     128
#define MROWS  (BATCH*SQ)   // 4096

// ---------------- scratch (allocation-free rule) ----------------
__device__ float  g_qkv [(size_t)MROWS * QKV_O];
__device__ float  g_attn[(size_t)MROWS * HID];
__device__ __half g_hs16  [(size_t)MROWS * HID];
__device__ __half g_wqkv16[(size_t)QKV_O * HID];
__device__ __half g_wo16  [(size_t)HID   * HID];
__device__ __half g_attn16[(size_t)MROWS * HID];

// ---------------- helpers ----------------
__device__ __forceinline__ uint32_t smem_u32(const void* p) {
    uint32_t a;
    asm("{ .reg .u64 t; cvta.to.shared.u64 t, %1; cvt.u32.u64 %0, t; }" : "=r"(a) : "l"(p));
    return a;
}
#define CP_ASYNC16(dst, src) \
    asm volatile("cp.async.cg.shared.global [%0], [%1], 16;" :: "r"(dst), "l"(src))
#define CP_COMMIT()  asm volatile("cp.async.commit_group;" ::: "memory")
#define CP_WAIT1()   asm volatile("cp.async.wait_group 1;" ::: "memory")
#define CP_WAIT0()   asm volatile("cp.async.wait_group 0;" ::: "memory")

__device__ __forceinline__ void ldm_x4(uint32_t& r0, uint32_t& r1, uint32_t& r2, uint32_t& r3,
                                       uint32_t addr) {
    asm volatile("ldmatrix.sync.aligned.m8n8.x4.shared.b16 {%0,%1,%2,%3}, [%4];"
                 : "=r"(r0), "=r"(r1), "=r"(r2), "=r"(r3) : "r"(addr));
}
__device__ __forceinline__ void mma16816(float* c, const uint32_t* a, uint32_t b0, uint32_t b1) {
    asm volatile("mma.sync.aligned.m16n8k16.row.col.f32.f16.f16.f32 "
                 "{%0,%1,%2,%3}, {%4,%5,%6,%7}, {%8,%9}, {%0,%1,%2,%3};"
                 : "+f"(c[0]), "+f"(c[1]), "+f"(c[2]), "+f"(c[3])
                 : "r"(a[0]), "r"(a[1]), "r"(a[2]), "r"(a[3]), "r"(b0), "r"(b1));
}

// ---------------------------------------------------------------------------
// fp16 mma.sync GEMM:  C[M,N] (fp32) = A16[M,K] * B16[N,K]^T
// CTA 128x128, BK=32, 256 threads (8 warps, 2x4 grid, 64x32 per warp).
// smem row stride 40 halfs (80B) -> conflict-free ldmatrix.
// ---------------------------------------------------------------------------
#define GLD 40

__global__ void __launch_bounds__(256, 2) hgemm_mma(
    const __half* __restrict__ A, const __half* __restrict__ B,
    float* __restrict__ C, int N, int K)
{
    __shared__ __align__(16) __half sA[2][128 * GLD];
    __shared__ __align__(16) __half sB[2][128 * GLD];

    const int tid  = threadIdx.x;
    const int lane = tid & 31;
    const int wid  = tid >> 5;
    const int wr   = wid >> 2;          // 0..1
    const int wc   = wid & 3;           // 0..3
    const int rowBase = blockIdx.y * 128;
    const int colBase = blockIdx.x * 128;

    const __half* Ab = A + (size_t)rowBase * K;
    const __half* Bb = B + (size_t)colBase * K;

    const uint32_t sAu[2] = { smem_u32(sA[0]), smem_u32(sA[1]) };
    const uint32_t sBu[2] = { smem_u32(sB[0]), smem_u32(sB[1]) };

    // loader: tile kt -> buffer buf (each thread: 2 chunks A + 2 chunks B)
    auto load_tile = [&](int buf, int kt) {
        const __half* a = Ab + kt * 32;
        const __half* b = Bb + kt * 32;
        #pragma unroll
        for (int it = 0; it < 2; ++it) {
            int idx = tid + it * 256;
            int r = idx >> 2, c = idx & 3;
            CP_ASYNC16(sAu[buf] + (r * GLD + c * 8) * 2, a + (size_t)r * K + c * 8);
        }
        #pragma unroll
        for (int it = 0; it < 2; ++it) {
            int idx = tid + it * 256;
            int r = idx >> 2, c = idx & 3;
            CP_ASYNC16(sBu[buf] + (r * GLD + c * 8) * 2, b + (size_t)r * K + c * 8);
        }
    };

    float acc[4][4][4];
    #pragma unroll
    for (int i = 0; i < 4; ++i)
        #pragma unroll
        for (int j = 0; j < 4; ++j)
            #pragma unroll
            for (int r = 0; r < 4; ++r) acc[i][j][r] = 0.f;

    // per-lane ldmatrix addressing
    const int g  = lane >> 3;           // 8-lane group 0..3
    const int lr = lane & 7;
    // A: groups -> (m+0,k+0),(m+8,k+0),(m+0,k+8),(m+8,k+8)
    const int a_row = wr * 64 + lr + (g & 1) * 8;
    const int a_kh  = (g >> 1) * 8;
    // B: groups -> (n+0,k+0),(n+0,k+8),(n+8,k+0),(n+8,k+8)
    const int b_row = wc * 32 + lr + (g >> 1) * 8;
    const int b_kh  = (g & 1) * 8;

    load_tile(0, 0);
    CP_COMMIT();

    const int NT = K / 32;
    for (int kt = 0; kt < NT; ++kt) {
        const int buf = kt & 1;
        if (kt + 1 < NT) { load_tile(buf ^ 1, kt + 1); CP_COMMIT(); CP_WAIT1(); }
        else             { CP_WAIT0(); }
        __syncthreads();

        #pragma unroll
        for (int s = 0; s < 2; ++s) {
            uint32_t af[4][4];
            #pragma unroll
            for (int i = 0; i < 4; ++i)
                ldm_x4(af[i][0], af[i][1], af[i][2], af[i][3],
                       sAu[buf] + ((a_row + i * 16) * GLD + s * 16 + a_kh) * 2);
            uint32_t bf[8];
            #pragma unroll
            for (int j2 = 0; j2 < 2; ++j2)
                ldm_x4(bf[j2 * 4 + 0], bf[j2 * 4 + 1], bf[j2 * 4 + 2], bf[j2 * 4 + 3],
                       sBu[buf] + ((b_row + j2 * 16) * GLD + s * 16 + b_kh) * 2);
            #pragma unroll
            for (int i = 0; i < 4; ++i)
                #pragma unroll
                for (int j = 0; j < 4; ++j)
                    mma16816(acc[i][j], af[i], bf[j * 2], bf[j * 2 + 1]);
        }
        __syncthreads();
    }

    // epilogue: fragment layout c0:(m=l/4, n=2(l%4)) c1:+1 c2:(m+8) c3:(m+8,+1)
    const int em = lane >> 2;
    const int en = (lane & 3) * 2;
    #pragma unroll
    for (int i = 0; i < 4; ++i) {
        int m0 = rowBase + wr * 64 + i * 16 + em;
        #pragma unroll
        for (int j = 0; j < 4; ++j) {
            int n0 = colBase + wc * 32 + j * 8 + en;
            *(float2*)(C + (size_t)m0 * N + n0)       = make_float2(acc[i][j][0], acc[i][j][1]);
            *(float2*)(C + (size_t)(m0 + 8) * N + n0) = make_float2(acc[i][j][2], acc[i][j][3]);
        }
    }
}

// ---------------------------------------------------------------------------
// fp32 -> fp16 conversion (vectorized by 4)
// ---------------------------------------------------------------------------
__global__ void cvt16(const float* __restrict__ in, __half* __restrict__ out, int n)
{
    int i = (blockIdx.x * blockDim.x + threadIdx.x) * 4;
    if (i >= n) return;
    float4 v = *(const float4*)(in + i);
    union { uint2 u; __half2 h[2]; } pk;
    pk.h[0] = __floats2half2_rn(v.x, v.y);
    pk.h[1] = __floats2half2_rn(v.z, v.w);
    *(uint2*)(out + i) = pk.u;
}

// ---------------------------------------------------------------------------
// RoPE in-place on Q (heads 0..31) and K (heads 32..39) inside g_qkv.
// ---------------------------------------------------------------------------
__global__ void rope_kernel(float* __restrict__ qkv, const int* __restrict__ positions)
{
    int idx = blockIdx.x * blockDim.x + threadIdx.x;
    int p = idx & 63;
    int h = (idx >> 6) % 40;
    int r = idx / (64 * 40);
    if (r >= MROWS) return;

    int col = (h < NHEADS) ? h * HD : HID + (h - NHEADS) * HD;
    float* base = qkv + (size_t)r * QKV_O + col;

    float pos = (float)positions[r];
    float inv = expf((float)p * (-13.815510557964274f / 64.f));
    float ang = pos * inv;
    float sn, cs;
    sincosf(ang, &sn, &cs);

    float x1 = base[p];
    float x2 = base[p + 64];
    base[p]      = x1 * cs - x2 * sn;
    base[p + 64] = x2 * cs + x1 * sn;
}

// ---------------------------------------------------------------------------
// Flash attention, fp32, causal, GQA (R=4). BM=BN=64, D=128, 256 threads.
// (unchanged from round 1 — passed with rel_err 1e-5)
// ---------------------------------------------------------------------------
#define BMA 64
#define BNA 64
#define QK_LD 65
#define PS_LD 68

__global__ void __launch_bounds__(256, 2) attn_kernel(
    const float* __restrict__ qkv, float* __restrict__ attn_out)
{
    extern __shared__ float sm[];
    float* Qs = sm;
    float* Ks = Qs + 128 * QK_LD;
    float* Vs = Ks + 128 * QK_LD;
    float* Ps = Ks;

    const int tid = threadIdx.x;
    const int tx = tid & 15;
    const int ty = tid >> 4;
    const int qt = blockIdx.x;
    const int h  = blockIdx.y;
    const int b  = blockIdx.z;
    const int g  = h >> 2;
    const float scale = 0.08838834764831845f;

    const float* qbase = qkv + ((size_t)(b * SQ + qt * BMA)) * QKV_O + h * HD;
    const float* kbase = qkv + ((size_t)(b * SQ)) * QKV_O + HID + g * HD;
    const float* vbase = qkv + ((size_t)(b * SQ)) * QKV_O + HID + KVH * HD + g * HD;

    for (int i = tid; i < BMA * 32; i += 256) {
        int n  = i >> 5;
        int d4 = (i & 31) * 4;
        float4 v = *(const float4*)(qbase + (size_t)n * QKV_O + d4);
        Qs[(d4 + 0) * QK_LD + n] = v.x * scale;
        Qs[(d4 + 1) * QK_LD + n] = v.y * scale;
        Qs[(d4 + 2) * QK_LD + n] = v.z * scale;
        Qs[(d4 + 3) * QK_LD + n] = v.w * scale;
    }

    float m_i[4], l_i[4], o[4][8];
    #pragma unroll
    for (int i = 0; i < 4; ++i) {
        m_i[i] = -1e30f; l_i[i] = 0.f;
        #pragma unroll
        for (int j = 0; j < 8; ++j) o[i][j] = 0.f;
    }

    const int nkt = qt + 1;
    for (int kt = 0; kt < nkt; ++kt) {
        __syncthreads();

        const float* kb = kbase + (size_t)(kt * BNA) * QKV_O;
        const float* vb = vbase + (size_t)(kt * BNA) * QKV_O;
        for (int i = tid; i < BNA * 32; i += 256) {
            int n  = i >> 5;
            int d4 = (i & 31) * 4;
            float4 v = *(const float4*)(kb + (size_t)n * QKV_O + d4);
            Ks[(d4 + 0) * QK_LD + n] = v.x;
            Ks[(d4 + 1) * QK_LD + n] = v.y;
            Ks[(d4 + 2) * QK_LD + n] = v.z;
            Ks[(d4 + 3) * QK_LD + n] = v.w;
            float4 w = *(const float4*)(vb + (size_t)n * QKV_O + d4);
            *(float4*)(Vs + n * 128 + d4) = w;
        }
        __syncthreads();

        float s[4][4];
        #pragma unroll
        for (int i = 0; i < 4; ++i)
            #pragma unroll
            for (int j = 0; j < 4; ++j) s[i][j] = 0.f;

        #pragma unroll 4
        for (int k = 0; k < 128; ++k) {
            float a[4], bb[4];
            #pragma unroll
            for (int i = 0; i < 4; ++i) a[i]  = Qs[k * QK_LD + ty * 4 + i];
            #pragma unroll
            for (int j = 0; j < 4; ++j) bb[j] = Ks[k * QK_LD + tx * 4 + j];
            #pragma unroll
            for (int i = 0; i < 4; ++i)
                #pragma unroll
                for (int j = 0; j < 4; ++j)
                    s[i][j] += a[i] * bb[j];
        }

        if (kt == qt) {
            #pragma unroll
            for (int i = 0; i < 4; ++i) {
                int qrow = ty * 4 + i;
                #pragma unroll
                for (int j = 0; j < 4; ++j)
                    if (tx * 4 + j > qrow) s[i][j] = -1e30f;
            }
        }

        float alpha[4], pr[4][4];
        #pragma unroll
        for (int i = 0; i < 4; ++i) {
            float tm = fmaxf(fmaxf(s[i][0], s[i][1]), fmaxf(s[i][2], s[i][3]));
            tm = fmaxf(tm, __shfl_xor_sync(0xffffffffu, tm, 1));
            tm = fmaxf(tm, __shfl_xor_sync(0xffffffffu, tm, 2));
            tm = fmaxf(tm, __shfl_xor_sync(0xffffffffu, tm, 4));
            tm = fmaxf(tm, __shfl_xor_sync(0xffffffffu, tm, 8));
            float mn = fmaxf(m_i[i], tm);
            alpha[i] = __expf(m_i[i] - mn);
            float rs = 0.f;
            #pragma unroll
            for (int j = 0; j < 4; ++j) {
                pr[i][j] = __expf(s[i][j] - mn);
                rs += pr[i][j];
            }
            rs += __shfl_xor_sync(0xffffffffu, rs, 1);
            rs += __shfl_xor_sync(0xffffffffu, rs, 2);
            rs += __shfl_xor_sync(0xffffffffu, rs, 4);
            rs += __shfl_xor_sync(0xffffffffu, rs, 8);
            l_i[i] = l_i[i] * alpha[i] + rs;
            m_i[i] = mn;
        }

        __syncthreads();

        #pragma unroll
        for (int i = 0; i < 4; ++i)
            *(float4*)(Ps + (ty * 4 + i) * PS_LD + tx * 4) =
                make_float4(pr[i][0], pr[i][1], pr[i][2], pr[i][3]);

        #pragma unroll
        for (int i = 0; i < 4; ++i)
            #pragma unroll
            for (int j = 0; j < 8; ++j) o[i][j] *= alpha[i];

        __syncthreads();

        #pragma unroll 2
        for (int kk = 0; kk < BNA; ++kk) {
            float p[4];
            #pragma unroll
            for (int i = 0; i < 4; ++i) p[i] = Ps[(ty * 4 + i) * PS_LD + kk];
            float4 va  = *(const float4*)(Vs + kk * 128 + tx * 8);
            float4 vb4 = *(const float4*)(Vs + kk * 128 + tx * 8 + 4);
            #pragma unroll
            for (int i = 0; i < 4; ++i) {
                o[i][0] += p[i] * va.x;  o[i][1] += p[i] * va.y;
                o[i][2] += p[i] * va.z;  o[i][3] += p[i] * va.w;
                o[i][4] += p[i] * vb4.x; o[i][5] += p[i] * vb4.y;
                o[i][6] += p[i] * vb4.z; o[i][7] += p[i] * vb4.w;
            }
        }
    }

    float* ob = attn_out + ((size_t)(b * SQ + qt * BMA)) * HID + h * HD;
    #pragma unroll
    for (int i = 0; i < 4; ++i) {
        float inv = 1.f / l_i[i];
        float4 v0 = make_float4(o[i][0] * inv, o[i][1] * inv, o[i][2] * inv, o[i][3] * inv);
        float4 v1 = make_float4(o[i][4] * inv, o[i][5] * inv, o[i][6] * inv, o[i][7] * inv);
        *(float4*)(ob + (size_t)(ty * 4 + i) * HID + tx * 8)     = v0;
        *(float4*)(ob + (size_t)(ty * 4 + i) * HID + tx * 8 + 4) = v1;
    }
}

// ---------------------------------------------------------------------------
extern "C" void kernel_launch(void* const* d_in, const int* in_sizes, int n_in,
                              void* d_out, int out_size)
{
    const float* hs   = (const float*)d_in[0];
    const int*   pos  = (const int*)  d_in[1];
    const float* wqkv = (const float*)d_in[2];
    const float* wo   = (const float*)d_in[3];
    float* out = (float*)d_out;

    float *qkv, *attn;
    __half *hs16, *wqkv16, *wo16, *attn16;
    cudaGetSymbolAddress((void**)&qkv,    g_qkv);
    cudaGetSymbolAddress((void**)&attn,   g_attn);
    cudaGetSymbolAddress((void**)&hs16,   g_hs16);
    cudaGetSymbolAddress((void**)&wqkv16, g_wqkv16);
    cudaGetSymbolAddress((void**)&wo16,   g_wo16);
    cudaGetSymbolAddress((void**)&attn16, g_attn16);

    // 0) fp32 -> fp16 conversions
    {
        int n;
        n = MROWS * HID;   cvt16<<<(n / 4 + 255) / 256, 256>>>(hs,   hs16,   n);
        n = QKV_O * HID;   cvt16<<<(n / 4 + 255) / 256, 256>>>(wqkv, wqkv16, n);
        n = HID * HID;     cvt16<<<(n / 4 + 255) / 256, 256>>>(wo,   wo16,   n);
    }

    // 1) QKV projection (fp16 tensor-core, fp32 accum)
    hgemm_mma<<<dim3(QKV_O / 128, MROWS / 128), 256>>>(hs16, wqkv16, qkv, QKV_O, HID);

    // 2) RoPE on Q + K heads
    {
        int total = MROWS * 40 * 64;
        rope_kernel<<<(total + 255) / 256, 256>>>(qkv, pos);
    }

    // 3) Flash attention (fp32)
    {
        size_t smem = (size_t)(128 * QK_LD * 2 + BNA * 128) * sizeof(float);
        cudaFuncSetAttribute(attn_kernel,
                             cudaFuncAttributeMaxDynamicSharedMemorySize, (int)smem);
        attn_kernel<<<dim3(SQ / BMA, NHEADS, BATCH), 256, smem>>>(qkv, attn);
    }

    // 4) attn fp32 -> fp16, then O projection
    {
        int n = MROWS * HID;
        cvt16<<<(n / 4 + 255) / 256, 256>>>(attn, attn16, n);
    }
    hgemm_mma<<<dim3(HID / 128, MROWS / 128), 256>>>(attn16, wo16, out, HID, HID);
}

// round 5
// speedup vs baseline: 6.7855x; 2.5493x over previous
#include <cuda_runtime.h>
#include <cuda_fp16.h>
#include <math.h>
#include <stdint.h>

#define SQ     2048
#define BATCH  2
#define HID    4096
#define QKV_O  6144
#define NHEADS 32
#define KVH    8
#define HD     128
#define MROWS  (BATCH*SQ)   // 4096

// ---------------- scratch (allocation-free rule) ----------------
__device__ float  g_qkv  [(size_t)MROWS * QKV_O];
__device__ __half g_qkv16[(size_t)MROWS * QKV_O];
__device__ __half g_hs16  [(size_t)MROWS * HID];
__device__ __half g_wqkv16[(size_t)QKV_O * HID];
__device__ __half g_wo16  [(size_t)HID   * HID];
__device__ __half g_attn16[(size_t)MROWS * HID];

// ---------------- helpers ----------------
__device__ __forceinline__ uint32_t smem_u32(const void* p) {
    uint32_t a;
    asm("{ .reg .u64 t; cvta.to.shared.u64 t, %1; cvt.u32.u64 %0, t; }" : "=r"(a) : "l"(p));
    return a;
}
#define CP_ASYNC16(dst, src) \
    asm volatile("cp.async.cg.shared.global [%0], [%1], 16;" :: "r"(dst), "l"(src))
#define CP_COMMIT()  asm volatile("cp.async.commit_group;" ::: "memory")
#define CP_WAIT1()   asm volatile("cp.async.wait_group 1;" ::: "memory")
#define CP_WAIT0()   asm volatile("cp.async.wait_group 0;" ::: "memory")

__device__ __forceinline__ void ldm_x4(uint32_t& r0, uint32_t& r1, uint32_t& r2, uint32_t& r3,
                                       uint32_t addr) {
    asm volatile("ldmatrix.sync.aligned.m8n8.x4.shared.b16 {%0,%1,%2,%3}, [%4];"
                 : "=r"(r0), "=r"(r1), "=r"(r2), "=r"(r3) : "r"(addr));
}
__device__ __forceinline__ void ldm_x4_t(uint32_t& r0, uint32_t& r1, uint32_t& r2, uint32_t& r3,
                                         uint32_t addr) {
    asm volatile("ldmatrix.sync.aligned.m8n8.x4.trans.shared.b16 {%0,%1,%2,%3}, [%4];"
                 : "=r"(r0), "=r"(r1), "=r"(r2), "=r"(r3) : "r"(addr));
}
__device__ __forceinline__ void mma16816(float* c, const uint32_t* a, uint32_t b0, uint32_t b1) {
    asm volatile("mma.sync.aligned.m16n8k16.row.col.f32.f16.f16.f32 "
                 "{%0,%1,%2,%3}, {%4,%5,%6,%7}, {%8,%9}, {%0,%1,%2,%3};"
                 : "+f"(c[0]), "+f"(c[1]), "+f"(c[2]), "+f"(c[3])
                 : "r"(a[0]), "r"(a[1]), "r"(a[2]), "r"(a[3]), "r"(b0), "r"(b1));
}
__device__ __forceinline__ uint32_t f22h(float a, float b) {
    union { __half2 h; uint32_t u; } x;
    x.h = __floats2half2_rn(a, b);
    return x.u;
}

// ---------------------------------------------------------------------------
// fp16 mma.sync GEMM:  C[M,N] (fp32) = A16[M,K] * B16[N,K]^T
// (unchanged from round 4 — measured 280 TF/s, tensor=52.5%)
// ---------------------------------------------------------------------------
#define GLD 40

__global__ void __launch_bounds__(256, 2) hgemm_mma(
    const __half* __restrict__ A, const __half* __restrict__ B,
    float* __restrict__ C, int N, int K)
{
    __shared__ __align__(16) __half sA[2][128 * GLD];
    __shared__ __align__(16) __half sB[2][128 * GLD];

    const int tid  = threadIdx.x;
    const int lane = tid & 31;
    const int wid  = tid >> 5;
    const int wr   = wid >> 2;
    const int wc   = wid & 3;
    const int rowBase = blockIdx.y * 128;
    const int colBase = blockIdx.x * 128;

    const __half* Ab = A + (size_t)rowBase * K;
    const __half* Bb = B + (size_t)colBase * K;

    const uint32_t sAu[2] = { smem_u32(sA[0]), smem_u32(sA[1]) };
    const uint32_t sBu[2] = { smem_u32(sB[0]), smem_u32(sB[1]) };

    auto load_tile = [&](int buf, int kt) {
        const __half* a = Ab + kt * 32;
        const __half* b = Bb + kt * 32;
        #pragma unroll
        for (int it = 0; it < 2; ++it) {
            int idx = tid + it * 256;
            int r = idx >> 2, c = idx & 3;
            CP_ASYNC16(sAu[buf] + (r * GLD + c * 8) * 2, a + (size_t)r * K + c * 8);
        }
        #pragma unroll
        for (int it = 0; it < 2; ++it) {
            int idx = tid + it * 256;
            int r = idx >> 2, c = idx & 3;
            CP_ASYNC16(sBu[buf] + (r * GLD + c * 8) * 2, b + (size_t)r * K + c * 8);
        }
    };

    float acc[4][4][4];
    #pragma unroll
    for (int i = 0; i < 4; ++i)
        #pragma unroll
        for (int j = 0; j < 4; ++j)
            #pragma unroll
            for (int r = 0; r < 4; ++r) acc[i][j][r] = 0.f;

    const int g  = lane >> 3;
    const int lr = lane & 7;
    const int a_row = wr * 64 + lr + (g & 1) * 8;
    const int a_kh  = (g >> 1) * 8;
    const int b_row = wc * 32 + lr + (g >> 1) * 8;
    const int b_kh  = (g & 1) * 8;

    load_tile(0, 0);
    CP_COMMIT();

    const int NT = K / 32;
    for (int kt = 0; kt < NT; ++kt) {
        const int buf = kt & 1;
        if (kt + 1 < NT) { load_tile(buf ^ 1, kt + 1); CP_COMMIT(); CP_WAIT1(); }
        else             { CP_WAIT0(); }
        __syncthreads();

        #pragma unroll
        for (int s = 0; s < 2; ++s) {
            uint32_t af[4][4];
            #pragma unroll
            for (int i = 0; i < 4; ++i)
                ldm_x4(af[i][0], af[i][1], af[i][2], af[i][3],
                       sAu[buf] + ((a_row + i * 16) * GLD + s * 16 + a_kh) * 2);
            uint32_t bf[8];
            #pragma unroll
            for (int j2 = 0; j2 < 2; ++j2)
                ldm_x4(bf[j2 * 4 + 0], bf[j2 * 4 + 1], bf[j2 * 4 + 2], bf[j2 * 4 + 3],
                       sBu[buf] + ((b_row + j2 * 16) * GLD + s * 16 + b_kh) * 2);
            #pragma unroll
            for (int i = 0; i < 4; ++i)
                #pragma unroll
                for (int j = 0; j < 4; ++j)
                    mma16816(acc[i][j], af[i], bf[j * 2], bf[j * 2 + 1]);
        }
        __syncthreads();
    }

    const int em = lane >> 2;
    const int en = (lane & 3) * 2;
    #pragma unroll
    for (int i = 0; i < 4; ++i) {
        int m0 = rowBase + wr * 64 + i * 16 + em;
        #pragma unroll
        for (int j = 0; j < 4; ++j) {
            int n0 = colBase + wc * 32 + j * 8 + en;
            *(float2*)(C + (size_t)m0 * N + n0)       = make_float2(acc[i][j][0], acc[i][j][1]);
            *(float2*)(C + (size_t)(m0 + 8) * N + n0) = make_float2(acc[i][j][2], acc[i][j][3]);
        }
    }
}

// ---------------------------------------------------------------------------
// fp32 -> fp16 conversion
// ---------------------------------------------------------------------------
__global__ void cvt16(const float* __restrict__ in, __half* __restrict__ out, int n)
{
    int i = (blockIdx.x * blockDim.x + threadIdx.x) * 4;
    if (i >= n) return;
    float4 v = *(const float4*)(in + i);
    union { uint2 u; __half2 h[2]; } pk;
    pk.h[0] = __floats2half2_rn(v.x, v.y);
    pk.h[1] = __floats2half2_rn(v.z, v.w);
    *(uint2*)(out + i) = pk.u;
}

// ---------------------------------------------------------------------------
// RoPE in-place (fp32) on Q + K heads of g_qkv.
// ---------------------------------------------------------------------------
__global__ void rope_kernel(float* __restrict__ qkv, const int* __restrict__ positions)
{
    int idx = blockIdx.x * blockDim.x + threadIdx.x;
    int p = idx & 63;
    int h = (idx >> 6) % 40;
    int r = idx / (64 * 40);
    if (r >= MROWS) return;

    int col = (h < NHEADS) ? h * HD : HID + (h - NHEADS) * HD;
    float* base = qkv + (size_t)r * QKV_O + col;

    float pos = (float)positions[r];
    float inv = expf((float)p * (-13.815510557964274f / 64.f));
    float ang = pos * inv;
    float sn, cs;
    sincosf(ang, &sn, &cs);

    float x1 = base[p];
    float x2 = base[p + 64];
    base[p]      = x1 * cs - x2 * sn;
    base[p + 64] = x2 * cs + x1 * sn;
}

// ---------------------------------------------------------------------------
// fp16 tensor-core flash attention, causal, GQA (R=4).
// BM=128 (8 warps x 16 rows), BN=64, D=128. Q frags in registers,
// K/V double-buffered cp.async smem (stride 136 halfs, conflict-free).
// Writes fp16 output directly.
// ---------------------------------------------------------------------------
#define KV_LD 136
#define KV_TILE (64 * KV_LD)          // halfs per K or V buffer
#define ATTN_SMEM (4 * KV_TILE * 2)   // bytes = 69632

__global__ void __launch_bounds__(256, 1) attn16_kernel(
    const __half* __restrict__ qkv16, __half* __restrict__ attnh)
{
    extern __shared__ __align__(16) __half smh[];
    const int tid  = threadIdx.x;
    const int lane = tid & 31;
    const int wm   = tid >> 5;          // warp id: q-row group
    const int lr   = lane & 7;
    const int lg   = lane >> 3;
    const int qt = blockIdx.x, h = blockIdx.y, b = blockIdx.z;
    const int g  = h >> 2;
    const float scale = 0.08838834764831845f;

    const uint32_t ks[2] = { smem_u32(smh),               smem_u32(smh + 2 * KV_TILE) };
    const uint32_t vs[2] = { smem_u32(smh + KV_TILE),     smem_u32(smh + 3 * KV_TILE) };

    const int t0 = b * SQ + qt * 128;
    const int r0 = lane >> 2;           // local row (and +8)
    const int c0 = (lane & 3) * 2;      // local col pair base

    // ---- Q fragments: 8 d-chunks x 4 regs, loaded once from gmem ----
    uint32_t qf[8][4];
    {
        const __half* qp = qkv16 + (size_t)(t0 + wm * 16) * QKV_O + h * HD;
        #pragma unroll
        for (int kc = 0; kc < 8; ++kc) {
            qf[kc][0] = *(const uint32_t*)(qp + (size_t)r0 * QKV_O + kc * 16 + c0);
            qf[kc][1] = *(const uint32_t*)(qp + (size_t)(r0 + 8) * QKV_O + kc * 16 + c0);
            qf[kc][2] = *(const uint32_t*)(qp + (size_t)r0 * QKV_O + kc * 16 + 8 + c0);
            qf[kc][3] = *(const uint32_t*)(qp + (size_t)(r0 + 8) * QKV_O + kc * 16 + 8 + c0);
        }
    }

    float o[16][4];
    #pragma unroll
    for (int i = 0; i < 16; ++i)
        #pragma unroll
        for (int r = 0; r < 4; ++r) o[i][r] = 0.f;
    float m_i[2] = { -1e30f, -1e30f };
    float l_i[2] = { 0.f, 0.f };

    const __half* kbase = qkv16 + (size_t)(b * SQ) * QKV_O + HID + g * HD;
    const __half* vbase = kbase + KVH * HD;

    auto load_kv = [&](int buf, int j) {
        const __half* kp = kbase + (size_t)(j * 64) * QKV_O;
        const __half* vp = vbase + (size_t)(j * 64) * QKV_O;
        #pragma unroll
        for (int it = 0; it < 4; ++it) {
            int c = tid + it * 256;
            int row = c >> 4, col = (c & 15) * 8;
            CP_ASYNC16(ks[buf] + (row * KV_LD + col) * 2, kp + (size_t)row * QKV_O + col);
            CP_ASYNC16(vs[buf] + (row * KV_LD + col) * 2, vp + (size_t)row * QKV_O + col);
        }
    };

    const int jmax = 2 * qt + 1;
    load_kv(0, 0);
    CP_COMMIT();

    for (int j = 0; j <= jmax; ++j) {
        const int buf = j & 1;
        if (j < jmax) { load_kv(buf ^ 1, j + 1); CP_COMMIT(); CP_WAIT1(); }
        else          { CP_WAIT0(); }
        __syncthreads();

        if (j * 64 <= qt * 128 + wm * 16 + 15) {   // skip fully-masked warp tiles
            // ---- S = Q K^T ----
            float s[8][4];
            #pragma unroll
            for (int nf = 0; nf < 8; ++nf)
                #pragma unroll
                for (int r = 0; r < 4; ++r) s[nf][r] = 0.f;

            #pragma unroll
            for (int kd = 0; kd < 8; ++kd) {
                uint32_t bf[4][4];
                #pragma unroll
                for (int q = 0; q < 4; ++q)
                    ldm_x4(bf[q][0], bf[q][1], bf[q][2], bf[q][3],
                           ks[buf] + ((q * 16 + lr + (lg >> 1) * 8) * KV_LD
                                      + kd * 16 + (lg & 1) * 8) * 2);
                #pragma unroll
                for (int nf = 0; nf < 8; ++nf)
                    mma16816(s[nf], qf[kd], bf[nf >> 1][(nf & 1) * 2],
                             bf[nf >> 1][(nf & 1) * 2 + 1]);
            }

            // ---- scale + causal mask ----
            #pragma unroll
            for (int nf = 0; nf < 8; ++nf)
                #pragma unroll
                for (int r = 0; r < 4; ++r) s[nf][r] *= scale;

            if (j >= 2 * qt) {
                const int gr0 = qt * 128 + wm * 16 + r0;
                #pragma unroll
                for (int nf = 0; nf < 8; ++nf) {
                    int col = j * 64 + nf * 8 + c0;
                    if (col     > gr0)     s[nf][0] = -1e30f;
                    if (col + 1 > gr0)     s[nf][1] = -1e30f;
                    if (col     > gr0 + 8) s[nf][2] = -1e30f;
                    if (col + 1 > gr0 + 8) s[nf][3] = -1e30f;
                }
            }

            // ---- online softmax ----
            float t0m = -1e30f, t1m = -1e30f;
            #pragma unroll
            for (int nf = 0; nf < 8; ++nf) {
                t0m = fmaxf(t0m, fmaxf(s[nf][0], s[nf][1]));
                t1m = fmaxf(t1m, fmaxf(s[nf][2], s[nf][3]));
            }
            t0m = fmaxf(t0m, __shfl_xor_sync(0xffffffffu, t0m, 1));
            t0m = fmaxf(t0m, __shfl_xor_sync(0xffffffffu, t0m, 2));
            t1m = fmaxf(t1m, __shfl_xor_sync(0xffffffffu, t1m, 1));
            t1m = fmaxf(t1m, __shfl_xor_sync(0xffffffffu, t1m, 2));

            const float mn0 = fmaxf(m_i[0], t0m);
            const float mn1 = fmaxf(m_i[1], t1m);
            const float a0 = __expf(m_i[0] - mn0);
            const float a1 = __expf(m_i[1] - mn1);
            m_i[0] = mn0; m_i[1] = mn1;

            float rs0 = 0.f, rs1 = 0.f;
            #pragma unroll
            for (int nf = 0; nf < 8; ++nf) {
                s[nf][0] = __expf(s[nf][0] - mn0);
                s[nf][1] = __expf(s[nf][1] - mn0);
                s[nf][2] = __expf(s[nf][2] - mn1);
                s[nf][3] = __expf(s[nf][3] - mn1);
                rs0 += s[nf][0] + s[nf][1];
                rs1 += s[nf][2] + s[nf][3];
            }
            rs0 += __shfl_xor_sync(0xffffffffu, rs0, 1);
            rs0 += __shfl_xor_sync(0xffffffffu, rs0, 2);
            rs1 += __shfl_xor_sync(0xffffffffu, rs1, 1);
            rs1 += __shfl_xor_sync(0xffffffffu, rs1, 2);
            l_i[0] = l_i[0] * a0 + rs0;
            l_i[1] = l_i[1] * a1 + rs1;

            #pragma unroll
            for (int of = 0; of < 16; ++of) {
                o[of][0] *= a0; o[of][1] *= a0;
                o[of][2] *= a1; o[of][3] *= a1;
            }

            // ---- pack P (no shuffles: C pairs == A pairs) ----
            uint32_t pa[4][4];
            #pragma unroll
            for (int kc = 0; kc < 4; ++kc) {
                pa[kc][0] = f22h(s[2 * kc][0],     s[2 * kc][1]);
                pa[kc][1] = f22h(s[2 * kc][2],     s[2 * kc][3]);
                pa[kc][2] = f22h(s[2 * kc + 1][0], s[2 * kc + 1][1]);
                pa[kc][3] = f22h(s[2 * kc + 1][2], s[2 * kc + 1][3]);
            }

            // ---- O += P V ----
            #pragma unroll
            for (int kc = 0; kc < 4; ++kc) {
                #pragma unroll
                for (int dg = 0; dg < 8; ++dg) {
                    uint32_t vb[4];
                    ldm_x4_t(vb[0], vb[1], vb[2], vb[3],
                             vs[buf] + ((kc * 16 + lr + (lg & 1) * 8) * KV_LD
                                        + dg * 16 + (lg >> 1) * 8) * 2);
                    mma16816(o[dg * 2],     pa[kc], vb[0], vb[1]);
                    mma16816(o[dg * 2 + 1], pa[kc], vb[2], vb[3]);
                }
            }
        }
        __syncthreads();
    }

    // ---- epilogue: normalize, write fp16 ----
    const float inv0 = 1.f / l_i[0];
    const float inv1 = 1.f / l_i[1];
    __half* op = attnh + (size_t)(t0 + wm * 16) * HID + h * HD;
    #pragma unroll
    for (int of = 0; of < 16; ++of) {
        int col = of * 8 + c0;
        *(uint32_t*)(op + (size_t)r0 * HID + col)       = f22h(o[of][0] * inv0, o[of][1] * inv0);
        *(uint32_t*)(op + (size_t)(r0 + 8) * HID + col) = f22h(o[of][2] * inv1, o[of][3] * inv1);
    }
}

// ---------------------------------------------------------------------------
extern "C" void kernel_launch(void* const* d_in, const int* in_sizes, int n_in,
                              void* d_out, int out_size)
{
    const float* hs   = (const float*)d_in[0];
    const int*   pos  = (const int*)  d_in[1];
    const float* wqkv = (const float*)d_in[2];
    const float* wo   = (const float*)d_in[3];
    float* out = (float*)d_out;

    float* qkv;
    __half *qkv16, *hs16, *wqkv16, *wo16, *attn16;
    cudaGetSymbolAddress((void**)&qkv,    g_qkv);
    cudaGetSymbolAddress((void**)&qkv16,  g_qkv16);
    cudaGetSymbolAddress((void**)&hs16,   g_hs16);
    cudaGetSymbolAddress((void**)&wqkv16, g_wqkv16);
    cudaGetSymbolAddress((void**)&wo16,   g_wo16);
    cudaGetSymbolAddress((void**)&attn16, g_attn16);

    // 0) fp32 -> fp16 input conversions
    {
        int n;
        n = MROWS * HID;   cvt16<<<(n / 4 + 255) / 256, 256>>>(hs,   hs16,   n);
        n = QKV_O * HID;   cvt16<<<(n / 4 + 255) / 256, 256>>>(wqkv, wqkv16, n);
        n = HID * HID;     cvt16<<<(n / 4 + 255) / 256, 256>>>(wo,   wo16,   n);
    }

    // 1) QKV projection (fp16 tensor-core, fp32 out)
    hgemm_mma<<<dim3(QKV_O / 128, MROWS / 128), 256>>>(hs16, wqkv16, qkv, QKV_O, HID);

    // 2) RoPE (fp32, in place)
    {
        int total = MROWS * 40 * 64;
        rope_kernel<<<(total + 255) / 256, 256>>>(qkv, pos);
    }

    // 3) qkv fp32 -> fp16 (single rounding for Q/K/V attention inputs)
    {
        int n = MROWS * QKV_O;
        cvt16<<<(n / 4 + 255) / 256, 256>>>(qkv, qkv16, n);
    }

    // 4) fp16 tensor-core flash attention -> fp16 out
    cudaFuncSetAttribute(attn16_kernel,
                         cudaFuncAttributeMaxDynamicSharedMemorySize, ATTN_SMEM);
    attn16_kernel<<<dim3(SQ / 128, NHEADS, BATCH), 256, ATTN_SMEM>>>(qkv16, attn16);

    // 5) O projection
    hgemm_mma<<<dim3(HID / 128, MROWS / 128), 256>>>(attn16, wo16, out, HID, HID);
}

// round 7
// speedup vs baseline: 7.5414x; 1.1114x over previous
#include <cuda_runtime.h>
#include <cuda_fp16.h>
#include <math.h>
#include <stdint.h>

#define SQ     2048
#define BATCH  2
#define HID    4096
#define QKV_O  6144
#define NHEADS 32
#define KVH    8
#define HD     128
#define MROWS  (BATCH*SQ)   // 4096

// ---------------- scratch (allocation-free rule) ----------------
__device__ float  g_qkv  [(size_t)MROWS * QKV_O];
__device__ __half g_qkv16[(size_t)MROWS * QKV_O];
__device__ __half g_hs16  [(size_t)MROWS * HID];
__device__ __half g_wqkv16[(size_t)QKV_O * HID];
__device__ __half g_wo16  [(size_t)HID   * HID];
__device__ __half g_attn16[(size_t)MROWS * HID];

// ---------------- helpers ----------------
__device__ __forceinline__ uint32_t smem_u32(const void* p) {
    uint32_t a;
    asm("{ .reg .u64 t; cvta.to.shared.u64 t, %1; cvt.u32.u64 %0, t; }" : "=r"(a) : "l"(p));
    return a;
}
#define CP_ASYNC16(dst, src) \
    asm volatile("cp.async.cg.shared.global [%0], [%1], 16;" :: "r"(dst), "l"(src))
#define CP_COMMIT()  asm volatile("cp.async.commit_group;" ::: "memory")
#define CP_WAIT1()   asm volatile("cp.async.wait_group 1;" ::: "memory")
#define CP_WAIT0()   asm volatile("cp.async.wait_group 0;" ::: "memory")

__device__ __forceinline__ void ldm_x4(uint32_t& r0, uint32_t& r1, uint32_t& r2, uint32_t& r3,
                                       uint32_t addr) {
    asm volatile("ldmatrix.sync.aligned.m8n8.x4.shared.b16 {%0,%1,%2,%3}, [%4];"
                 : "=r"(r0), "=r"(r1), "=r"(r2), "=r"(r3) : "r"(addr));
}
__device__ __forceinline__ void ldm_x4_t(uint32_t& r0, uint32_t& r1, uint32_t& r2, uint32_t& r3,
                                         uint32_t addr) {
    asm volatile("ldmatrix.sync.aligned.m8n8.x4.trans.shared.b16 {%0,%1,%2,%3}, [%4];"
                 : "=r"(r0), "=r"(r1), "=r"(r2), "=r"(r3) : "r"(addr));
}
__device__ __forceinline__ void mma16816(float* c, const uint32_t* a, uint32_t b0, uint32_t b1) {
    asm volatile("mma.sync.aligned.m16n8k16.row.col.f32.f16.f16.f32 "
                 "{%0,%1,%2,%3}, {%4,%5,%6,%7}, {%8,%9}, {%0,%1,%2,%3};"
                 : "+f"(c[0]), "+f"(c[1]), "+f"(c[2]), "+f"(c[3])
                 : "r"(a[0]), "r"(a[1]), "r"(a[2]), "r"(a[3]), "r"(b0), "r"(b1));
}
__device__ __forceinline__ uint32_t f22h(float a, float b) {
    union { __half2 h; uint32_t u; } x;
    x.h = __floats2half2_rn(a, b);
    return x.u;
}

// ---------------------------------------------------------------------------
// fp16 mma.sync GEMM:  C[M,N] (fp32) = A16[M,K] * B16[N,K]^T
// CTA 128x128, BK=64 (halved barrier count vs round 4), 2-stage cp.async,
// dynamic smem 72KB, 2 CTAs/SM. Row stride 72 halfs -> conflict-free ldmatrix.
// ---------------------------------------------------------------------------
#define GLD2 72
#define GSTG (128 * GLD2)                  // halfs per (A or B) stage
#define GEMM_SMEM (4 * GSTG * 2)           // bytes = 73728

__global__ void __launch_bounds__(256, 2) hgemm_mma(
    const __half* __restrict__ A, const __half* __restrict__ B,
    float* __restrict__ C, int N, int K)
{
    extern __shared__ __align__(16) __half smg[];
    const uint32_t sAu[2] = { smem_u32(smg),            smem_u32(smg + 2 * GSTG) };
    const uint32_t sBu[2] = { smem_u32(smg + GSTG),     smem_u32(smg + 3 * GSTG) };

    const int tid  = threadIdx.x;
    const int lane = tid & 31;
    const int wid  = tid >> 5;
    const int wr   = wid >> 2;
    const int wc   = wid & 3;
    const int rowBase = blockIdx.y * 128;
    const int colBase = blockIdx.x * 128;

    const __half* Ab = A + (size_t)rowBase * K;
    const __half* Bb = B + (size_t)colBase * K;

    // tile kt (BK=64): each thread copies 4 chunks A + 4 chunks B (16B each)
    auto load_tile = [&](int buf, int kt) {
        const __half* a = Ab + kt * 64;
        const __half* b = Bb + kt * 64;
        #pragma unroll
        for (int it = 0; it < 4; ++it) {
            int idx = tid + it * 256;          // 0..1023
            int r = idx >> 3, c = idx & 7;
            CP_ASYNC16(sAu[buf] + (r * GLD2 + c * 8) * 2, a + (size_t)r * K + c * 8);
        }
        #pragma unroll
        for (int it = 0; it < 4; ++it) {
            int idx = tid + it * 256;
            int r = idx >> 3, c = idx & 7;
            CP_ASYNC16(sBu[buf] + (r * GLD2 + c * 8) * 2, b + (size_t)r * K + c * 8);
        }
    };

    float acc[4][4][4];
    #pragma unroll
    for (int i = 0; i < 4; ++i)
        #pragma unroll
        for (int j = 0; j < 4; ++j)
            #pragma unroll
            for (int r = 0; r < 4; ++r) acc[i][j][r] = 0.f;

    const int g  = lane >> 3;
    const int lr = lane & 7;
    const int a_row = wr * 64 + lr + (g & 1) * 8;
    const int a_kh  = (g >> 1) * 8;
    const int b_row = wc * 32 + lr + (g >> 1) * 8;
    const int b_kh  = (g & 1) * 8;

    load_tile(0, 0);
    CP_COMMIT();

    const int NT = K / 64;
    for (int kt = 0; kt < NT; ++kt) {
        const int buf = kt & 1;
        if (kt + 1 < NT) { load_tile(buf ^ 1, kt + 1); CP_COMMIT(); CP_WAIT1(); }
        else             { CP_WAIT0(); }
        __syncthreads();

        #pragma unroll
        for (int s = 0; s < 4; ++s) {
            uint32_t af[4][4];
            #pragma unroll
            for (int i = 0; i < 4; ++i)
                ldm_x4(af[i][0], af[i][1], af[i][2], af[i][3],
                       sAu[buf] + ((a_row + i * 16) * GLD2 + s * 16 + a_kh) * 2);
            uint32_t bf[8];
            #pragma unroll
            for (int j2 = 0; j2 < 2; ++j2)
                ldm_x4(bf[j2 * 4 + 0], bf[j2 * 4 + 1], bf[j2 * 4 + 2], bf[j2 * 4 + 3],
                       sBu[buf] + ((b_row + j2 * 16) * GLD2 + s * 16 + b_kh) * 2);
            #pragma unroll
            for (int i = 0; i < 4; ++i)
                #pragma unroll
                for (int j = 0; j < 4; ++j)
                    mma16816(acc[i][j], af[i], bf[j * 2], bf[j * 2 + 1]);
        }
        __syncthreads();
    }

    const int em = lane >> 2;
    const int en = (lane & 3) * 2;
    #pragma unroll
    for (int i = 0; i < 4; ++i) {
        int m0 = rowBase + wr * 64 + i * 16 + em;
        #pragma unroll
        for (int j = 0; j < 4; ++j) {
            int n0 = colBase + wc * 32 + j * 8 + en;
            *(float2*)(C + (size_t)m0 * N + n0)       = make_float2(acc[i][j][0], acc[i][j][1]);
            *(float2*)(C + (size_t)(m0 + 8) * N + n0) = make_float2(acc[i][j][2], acc[i][j][3]);
        }
    }
}

// ---------------------------------------------------------------------------
// fp32 -> fp16 conversion (inputs/weights)
// ---------------------------------------------------------------------------
__global__ void cvt16(const float* __restrict__ in, __half* __restrict__ out, int n)
{
    int i = (blockIdx.x * blockDim.x + threadIdx.x) * 4;
    if (i >= n) return;
    float4 v = *(const float4*)(in + i);
    union { uint2 u; __half2 h[2]; } pk;
    pk.h[0] = __floats2half2_rn(v.x, v.y);
    pk.h[1] = __floats2half2_rn(v.z, v.w);
    *(uint2*)(out + i) = pk.u;
}

// ---------------------------------------------------------------------------
// Fused RoPE + fp32->fp16: reads g_qkv (fp32), applies RoPE to Q/K heads,
// plain-converts V, writes g_qkv16. One pass instead of rope + full cvt.
// Per row: 2560 rope-pair threads (40 heads x 64 pairs) + 512 V half2 threads.
// ---------------------------------------------------------------------------
__global__ void rope_cvt(const float* __restrict__ qkv, __half* __restrict__ qkv16,
                         const int* __restrict__ positions)
{
    int t = blockIdx.x * blockDim.x + threadIdx.x;
    int r = t / 3072;
    int u = t - r * 3072;
    if (r >= MROWS) return;

    const float* src = qkv   + (size_t)r * QKV_O;
    __half*      dst = qkv16 + (size_t)r * QKV_O;

    if (u < 2560) {
        int h = u >> 6, p = u & 63;
        int col = (h < NHEADS) ? h * HD : HID + (h - NHEADS) * HD;
        float pos = (float)positions[r];
        float inv = expf((float)p * (-13.815510557964274f / 64.f));
        float ang = pos * inv;
        float sn, cs;
        sincosf(ang, &sn, &cs);
        float x1 = src[col + p];
        float x2 = src[col + p + 64];
        dst[col + p]      = __float2half_rn(x1 * cs - x2 * sn);
        dst[col + p + 64] = __float2half_rn(x2 * cs + x1 * sn);
    } else {
        int c = 5120 + ((u - 2560) << 1);
        float2 v = *(const float2*)(src + c);
        *(__half2*)(dst + c) = __floats2half2_rn(v.x, v.y);
    }
}

// ---------------------------------------------------------------------------
// fp16 tensor-core flash attention, causal, GQA (R=4).  (unchanged — passed
// at 1593 us total) BM=128 (8 warps x 16 rows), BN=64, D=128.
// ---------------------------------------------------------------------------
#define KV_LD 136
#define KV_TILE (64 * KV_LD)
#define ATTN_SMEM (4 * KV_TILE * 2)

__global__ void __launch_bounds__(256, 1) attn16_kernel(
    const __half* __restrict__ qkv16, __half* __restrict__ attnh)
{
    extern __shared__ __align__(16) __half smh[];
    const int tid  = threadIdx.x;
    const int lane = tid & 31;
    const int wm   = tid >> 5;
    const int lr   = lane & 7;
    const int lg   = lane >> 3;
    const int qt = blockIdx.x, h = blockIdx.y, b = blockIdx.z;
    const int g  = h >> 2;
    const float scale = 0.08838834764831845f;

    const uint32_t ks[2] = { smem_u32(smh),           smem_u32(smh + 2 * KV_TILE) };
    const uint32_t vs[2] = { smem_u32(smh + KV_TILE), smem_u32(smh + 3 * KV_TILE) };

    const int t0 = b * SQ + qt * 128;
    const int r0 = lane >> 2;
    const int c0 = (lane & 3) * 2;

    uint32_t qf[8][4];
    {
        const __half* qp = qkv16 + (size_t)(t0 + wm * 16) * QKV_O + h * HD;
        #pragma unroll
        for (int kc = 0; kc < 8; ++kc) {
            qf[kc][0] = *(const uint32_t*)(qp + (size_t)r0 * QKV_O + kc * 16 + c0);
            qf[kc][1] = *(const uint32_t*)(qp + (size_t)(r0 + 8) * QKV_O + kc * 16 + c0);
            qf[kc][2] = *(const uint32_t*)(qp + (size_t)r0 * QKV_O + kc * 16 + 8 + c0);
            qf[kc][3] = *(const uint32_t*)(qp + (size_t)(r0 + 8) * QKV_O + kc * 16 + 8 + c0);
        }
    }

    float o[16][4];
    #pragma unroll
    for (int i = 0; i < 16; ++i)
        #pragma unroll
        for (int r = 0; r < 4; ++r) o[i][r] = 0.f;
    float m_i[2] = { -1e30f, -1e30f };
    float l_i[2] = { 0.f, 0.f };

    const __half* kbase = qkv16 + (size_t)(b * SQ) * QKV_O + HID + g * HD;
    const __half* vbase = kbase + KVH * HD;

    auto load_kv = [&](int buf, int j) {
        const __half* kp = kbase + (size_t)(j * 64) * QKV_O;
        const __half* vp = vbase + (size_t)(j * 64) * QKV_O;
        #pragma unroll
        for (int it = 0; it < 4; ++it) {
            int c = tid + it * 256;
            int row = c >> 4, col = (c & 15) * 8;
            CP_ASYNC16(ks[buf] + (row * KV_LD + col) * 2, kp + (size_t)row * QKV_O + col);
            CP_ASYNC16(vs[buf] + (row * KV_LD + col) * 2, vp + (size_t)row * QKV_O + col);
        }
    };

    const int jmax = 2 * qt + 1;
    load_kv(0, 0);
    CP_COMMIT();

    for (int j = 0; j <= jmax; ++j) {
        const int buf = j & 1;
        if (j < jmax) { load_kv(buf ^ 1, j + 1); CP_COMMIT(); CP_WAIT1(); }
        else          { CP_WAIT0(); }
        __syncthreads();

        if (j * 64 <= qt * 128 + wm * 16 + 15) {
            float s[8][4];
            #pragma unroll
            for (int nf = 0; nf < 8; ++nf)
                #pragma unroll
                for (int r = 0; r < 4; ++r) s[nf][r] = 0.f;

            #pragma unroll
            for (int kd = 0; kd < 8; ++kd) {
                uint32_t bf[4][4];
                #pragma unroll
                for (int q = 0; q < 4; ++q)
                    ldm_x4(bf[q][0], bf[q][1], bf[q][2], bf[q][3],
                           ks[buf] + ((q * 16 + lr + (lg >> 1) * 8) * KV_LD
                                      + kd * 16 + (lg & 1) * 8) * 2);
                #pragma unroll
                for (int nf = 0; nf < 8; ++nf)
                    mma16816(s[nf], qf[kd], bf[nf >> 1][(nf & 1) * 2],
                             bf[nf >> 1][(nf & 1) * 2 + 1]);
            }

            #pragma unroll
            for (int nf = 0; nf < 8; ++nf)
                #pragma unroll
                for (int r = 0; r < 4; ++r) s[nf][r] *= scale;

            if (j >= 2 * qt) {
                const int gr0 = qt * 128 + wm * 16 + r0;
                #pragma unroll
                for (int nf = 0; nf < 8; ++nf) {
                    int col = j * 64 + nf * 8 + c0;
                    if (col     > gr0)     s[nf][0] = -1e30f;
                    if (col + 1 > gr0)     s[nf][1] = -1e30f;
                    if (col     > gr0 + 8) s[nf][2] = -1e30f;
                    if (col + 1 > gr0 + 8) s[nf][3] = -1e30f;
                }
            }

            float t0m = -1e30f, t1m = -1e30f;
            #pragma unroll
            for (int nf = 0; nf < 8; ++nf) {
                t0m = fmaxf(t0m, fmaxf(s[nf][0], s[nf][1]));
                t1m = fmaxf(t1m, fmaxf(s[nf][2], s[nf][3]));
            }
            t0m = fmaxf(t0m, __shfl_xor_sync(0xffffffffu, t0m, 1));
            t0m = fmaxf(t0m, __shfl_xor_sync(0xffffffffu, t0m, 2));
            t1m = fmaxf(t1m, __shfl_xor_sync(0xffffffffu, t1m, 1));
            t1m = fmaxf(t1m, __shfl_xor_sync(0xffffffffu, t1m, 2));

            const float mn0 = fmaxf(m_i[0], t0m);
            const float mn1 = fmaxf(m_i[1], t1m);
            const float a0 = __expf(m_i[0] - mn0);
            const float a1 = __expf(m_i[1] - mn1);
            m_i[0] = mn0; m_i[1] = mn1;

            float rs0 = 0.f, rs1 = 0.f;
            #pragma unroll
            for (int nf = 0; nf < 8; ++nf) {
                s[nf][0] = __expf(s[nf][0] - mn0);
                s[nf][1] = __expf(s[nf][1] - mn0);
                s[nf][2] = __expf(s[nf][2] - mn1);
                s[nf][3] = __expf(s[nf][3] - mn1);
                rs0 += s[nf][0] + s[nf][1];
                rs1 += s[nf][2] + s[nf][3];
            }
            rs0 += __shfl_xor_sync(0xffffffffu, rs0, 1);
            rs0 += __shfl_xor_sync(0xffffffffu, rs0, 2);
            rs1 += __shfl_xor_sync(0xffffffffu, rs1, 1);
            rs1 += __shfl_xor_sync(0xffffffffu, rs1, 2);
            l_i[0] = l_i[0] * a0 + rs0;
            l_i[1] = l_i[1] * a1 + rs1;

            #pragma unroll
            for (int of = 0; of < 16; ++of) {
                o[of][0] *= a0; o[of][1] *= a0;
                o[of][2] *= a1; o[of][3] *= a1;
            }

            uint32_t pa[4][4];
            #pragma unroll
            for (int kc = 0; kc < 4; ++kc) {
                pa[kc][0] = f22h(s[2 * kc][0],     s[2 * kc][1]);
                pa[kc][1] = f22h(s[2 * kc][2],     s[2 * kc][3]);
                pa[kc][2] = f22h(s[2 * kc + 1][0], s[2 * kc + 1][1]);
                pa[kc][3] = f22h(s[2 * kc + 1][2], s[2 * kc + 1][3]);
            }

            #pragma unroll
            for (int kc = 0; kc < 4; ++kc) {
                #pragma unroll
                for (int dg = 0; dg < 8; ++dg) {
                    uint32_t vb[4];
                    ldm_x4_t(vb[0], vb[1], vb[2], vb[3],
                             vs[buf] + ((kc * 16 + lr + (lg & 1) * 8) * KV_LD
                                        + dg * 16 + (lg >> 1) * 8) * 2);
                    mma16816(o[dg * 2],     pa[kc], vb[0], vb[1]);
                    mma16816(o[dg * 2 + 1], pa[kc], vb[2], vb[3]);
                }
            }
        }
        __syncthreads();
    }

    const float inv0 = 1.f / l_i[0];
    const float inv1 = 1.f / l_i[1];
    __half* op = attnh + (size_t)(t0 + wm * 16) * HID + h * HD;
    #pragma unroll
    for (int of = 0; of < 16; ++of) {
        int col = of * 8 + c0;
        *(uint32_t*)(op + (size_t)r0 * HID + col)       = f22h(o[of][0] * inv0, o[of][1] * inv0);
        *(uint32_t*)(op + (size_t)(r0 + 8) * HID + col) = f22h(o[of][2] * inv1, o[of][3] * inv1);
    }
}

// ---------------------------------------------------------------------------
extern "C" void kernel_launch(void* const* d_in, const int* in_sizes, int n_in,
                              void* d_out, int out_size)
{
    const float* hs   = (const float*)d_in[0];
    const int*   pos  = (const int*)  d_in[1];
    const float* wqkv = (const float*)d_in[2];
    const float* wo   = (const float*)d_in[3];
    float* out = (float*)d_out;

    float* qkv;
    __half *qkv16, *hs16, *wqkv16, *wo16, *attn16;
    cudaGetSymbolAddress((void**)&qkv,    g_qkv);
    cudaGetSymbolAddress((void**)&qkv16,  g_qkv16);
    cudaGetSymbolAddress((void**)&hs16,   g_hs16);
    cudaGetSymbolAddress((void**)&wqkv16, g_wqkv16);
    cudaGetSymbolAddress((void**)&wo16,   g_wo16);
    cudaGetSymbolAddress((void**)&attn16, g_attn16);

    cudaFuncSetAttribute(hgemm_mma, cudaFuncAttributeMaxDynamicSharedMemorySize, GEMM_SMEM);
    cudaFuncSetAttribute(attn16_kernel, cudaFuncAttributeMaxDynamicSharedMemorySize, ATTN_SMEM);

    // 0) fp32 -> fp16 input conversions
    {
        int n;
        n = MROWS * HID;   cvt16<<<(n / 4 + 255) / 256, 256>>>(hs,   hs16,   n);
        n = QKV_O * HID;   cvt16<<<(n / 4 + 255) / 256, 256>>>(wqkv, wqkv16, n);
        n = HID * HID;     cvt16<<<(n / 4 + 255) / 256, 256>>>(wo,   wo16,   n);
    }

    // 1) QKV projection (fp16 tensor-core, fp32 out)
    hgemm_mma<<<dim3(QKV_O / 128, MROWS / 128), 256, GEMM_SMEM>>>(
        hs16, wqkv16, qkv, QKV_O, HID);

    // 2) fused RoPE + fp32->fp16 (single pass over qkv)
    {
        int total = MROWS * 3072;
        rope_cvt<<<(total + 255) / 256, 256>>>(qkv, qkv16, pos);
    }

    // 3) fp16 tensor-core flash attention -> fp16 out
    attn16_kernel<<<dim3(SQ / 128, NHEADS, BATCH), 256, ATTN_SMEM>>>(qkv16, attn16);

    // 4) O projection
    hgemm_mma<<<dim3(HID / 128, MROWS / 128), 256, GEMM_SMEM>>>(
        attn16, wo16, out, HID, HID);
}